// round 1
// baseline (speedup 1.0000x reference)
#include <cuda_runtime.h>
#include <cstdint>

#define E_N 100000
#define R_N 64
#define I_N 256
#define O_N 256
#define T_E 16

// 4 partial W reductions (summed at main-kernel start). 256 KB device scratch.
__device__ float g_wpart[4 * R_N * O_N];

// ---------------------------------------------------------------------------
// Kernel 1: partial reduction of W over i.  W[r][i][o], r=blockIdx.x,
// i-quarter = blockIdx.y. Coalesced: consecutive threads -> consecutive o.
// ---------------------------------------------------------------------------
__global__ void wsum_part_kernel(const float* __restrict__ W) {
    const int r = blockIdx.x;
    const int part = blockIdx.y;          // 0..3, covers i in [64*part, 64*part+64)
    const int o = threadIdx.x;            // 0..255
    const float* base = W + ((size_t)(r * I_N + part * 64)) * O_N + o;
    float s = 0.f;
#pragma unroll 16
    for (int i = 0; i < 64; ++i) s += base[(size_t)i * O_N];
    g_wpart[(part * R_N + r) * O_N + o] = s;
}

// ---------------------------------------------------------------------------
// Kernel 2: fused  out[e,o] = x_sum[e] * sum_r (1/cs[e,r]) * Wsum[r,o]
// 256 threads = 256 output columns; Wsum column lives in 64 dup'd f32x2 regs.
// Per iteration: 16 entities. Inner loop per r: 4 broadcast LDS.v2.u64
// (8 entity-pair multipliers) + 8 fma.rn.f32x2.
// ---------------------------------------------------------------------------
__global__ __launch_bounds__(256, 1)
void rgcn_main_kernel(const float* __restrict__ x,
                      const float* __restrict__ cs,
                      float* __restrict__ out, int chunk) {
    __shared__ float s_xs[T_E];
    __shared__ __align__(16) float2 s_a[R_N][T_E / 2];   // [r][entity-pair]

    const int t = threadIdx.x;

    // --- load Wsum column o=t, duplicated into b64 {w,w} registers ---------
    unsigned long long wd[R_N];
#pragma unroll
    for (int r = 0; r < R_N; ++r) {
        float w = g_wpart[r * O_N + t]
                + g_wpart[(R_N + r) * O_N + t]
                + g_wpart[(2 * R_N + r) * O_N + t]
                + g_wpart[(3 * R_N + r) * O_N + t];
        asm("mov.b64 %0, {%1, %1};" : "=l"(wd[r]) : "f"(w));
    }

    const int e_begin = blockIdx.x * chunk;
    const int e_end = min(E_N, e_begin + chunk);
    if (e_begin >= e_end) return;

    // A1 mapping: 16 threads per entity row-sum
    const int el1 = t >> 4;               // entity slot 0..15
    const int part = t & 15;              // 16-lane reduction group
    // A2 mapping: thread -> (entity pair p2, r pair rq)
    const int p2 = t & 7;                 // entity pair 0..7
    const int rq = t >> 3;                // 0..31 -> r = 2*rq, 2*rq+1

    const float4* __restrict__ x4 = (const float4*)x;
    const float2* __restrict__ cs2 = (const float2*)cs;

    const uint32_t sa_base = (uint32_t)__cvta_generic_to_shared(&s_a[0][0]);

    // --- initial prefetch (clamped indices; OOB-entity values never stored)
    float4 xv0, xv1, xv2, xv3;
    float2 cva, cvb;
    {
        int e1 = min(e_begin + el1, E_N - 1);
        const float4* xp = x4 + (size_t)e1 * 64 + part;
        xv0 = xp[0]; xv1 = xp[16]; xv2 = xp[32]; xv3 = xp[48];
        int eA = min(e_begin + 2 * p2, E_N - 1);
        int eB = min(e_begin + 2 * p2 + 1, E_N - 1);
        cva = cs2[(size_t)eA * 32 + rq];
        cvb = cs2[(size_t)eB * 32 + rq];
    }

    for (int e0 = e_begin; e0 < e_end; e0 += T_E) {
        // ---- A1: x row-sums (width-16 shuffle reduce) ----------------------
        float ps = xv0.x + xv0.y + xv0.z + xv0.w
                 + xv1.x + xv1.y + xv1.z + xv1.w
                 + xv2.x + xv2.y + xv2.z + xv2.w
                 + xv3.x + xv3.y + xv3.z + xv3.w;
        ps += __shfl_xor_sync(0xffffffffu, ps, 8, 16);
        ps += __shfl_xor_sync(0xffffffffu, ps, 4, 16);
        ps += __shfl_xor_sync(0xffffffffu, ps, 2, 16);
        ps += __shfl_xor_sync(0xffffffffu, ps, 1, 16);
        if (part == 0) s_xs[el1] = ps;
        __syncthreads();   // s_xs ready; also fences prev-iter s_a reads

        // ---- A2: a[r][e] = x_sum[e] / cs[e,r], stored as entity pairs ------
        float2 xsp = *(const float2*)&s_xs[2 * p2];
        float2 r0, r1;
        r0.x = __fdividef(xsp.x, cva.x);
        r0.y = __fdividef(xsp.y, cvb.x);
        r1.x = __fdividef(xsp.x, cva.y);
        r1.y = __fdividef(xsp.y, cvb.y);
        s_a[2 * rq][p2]     = r0;
        s_a[2 * rq + 1][p2] = r1;

        // ---- prefetch next iteration's x / cs (hidden under FMA phase) -----
        {
            int ne = e0 + T_E;
            int e1 = min(ne + el1, E_N - 1);
            const float4* xp = x4 + (size_t)e1 * 64 + part;
            xv0 = xp[0]; xv1 = xp[16]; xv2 = xp[32]; xv3 = xp[48];
            int eA = min(ne + 2 * p2, E_N - 1);
            int eB = min(ne + 2 * p2 + 1, E_N - 1);
            cva = cs2[(size_t)eA * 32 + rq];
            cvb = cs2[(size_t)eB * 32 + rq];
        }
        __syncthreads();   // s_a ready

        // ---- B: 64-step dual-rate FMA loop --------------------------------
        unsigned long long acc0 = 0, acc1 = 0, acc2 = 0, acc3 = 0,
                           acc4 = 0, acc5 = 0, acc6 = 0, acc7 = 0;
#pragma unroll
        for (int r = 0; r < R_N; ++r) {
            unsigned long long a0, a1, a2, a3, a4, a5, a6, a7;
            uint32_t ad = sa_base + r * 64;
            asm("ld.shared.v2.u64 {%0,%1},[%2];"    : "=l"(a0), "=l"(a1) : "r"(ad));
            asm("ld.shared.v2.u64 {%0,%1},[%2+16];" : "=l"(a2), "=l"(a3) : "r"(ad));
            asm("ld.shared.v2.u64 {%0,%1},[%2+32];" : "=l"(a4), "=l"(a5) : "r"(ad));
            asm("ld.shared.v2.u64 {%0,%1},[%2+48];" : "=l"(a6), "=l"(a7) : "r"(ad));
            asm("fma.rn.f32x2 %0,%1,%2,%0;" : "+l"(acc0) : "l"(a0), "l"(wd[r]));
            asm("fma.rn.f32x2 %0,%1,%2,%0;" : "+l"(acc1) : "l"(a1), "l"(wd[r]));
            asm("fma.rn.f32x2 %0,%1,%2,%0;" : "+l"(acc2) : "l"(a2), "l"(wd[r]));
            asm("fma.rn.f32x2 %0,%1,%2,%0;" : "+l"(acc3) : "l"(a3), "l"(wd[r]));
            asm("fma.rn.f32x2 %0,%1,%2,%0;" : "+l"(acc4) : "l"(a4), "l"(wd[r]));
            asm("fma.rn.f32x2 %0,%1,%2,%0;" : "+l"(acc5) : "l"(a5), "l"(wd[r]));
            asm("fma.rn.f32x2 %0,%1,%2,%0;" : "+l"(acc6) : "l"(a6), "l"(wd[r]));
            asm("fma.rn.f32x2 %0,%1,%2,%0;" : "+l"(acc7) : "l"(a7), "l"(wd[r]));
        }

        // ---- epilogue: unpack + guarded stores (coalesced per entity) ------
        float lo, hi;
#define RGCN_STORE(S, ACC)                                                   \
        {                                                                    \
            asm("mov.b64 {%0,%1},%2;" : "=f"(lo), "=f"(hi) : "l"(ACC));     \
            int ea = e0 + 2 * (S);                                           \
            if (ea < e_end)     out[(size_t)ea * O_N + t] = lo;              \
            if (ea + 1 < e_end) out[(size_t)(ea + 1) * O_N + t] = hi;        \
        }
        RGCN_STORE(0, acc0) RGCN_STORE(1, acc1) RGCN_STORE(2, acc2)
        RGCN_STORE(3, acc3) RGCN_STORE(4, acc4) RGCN_STORE(5, acc5)
        RGCN_STORE(6, acc6) RGCN_STORE(7, acc7)
#undef RGCN_STORE
    }
}

// ---------------------------------------------------------------------------
// Inputs (metadata order): x[E,256] f32, cs[E,64] f32, W[64,256,256] f32,
// edge_index[2,1.6M] i64 (dead in the factorized reference). Output f32 [E,256].
// ---------------------------------------------------------------------------
extern "C" void kernel_launch(void* const* d_in, const int* in_sizes, int n_in,
                              void* d_out, int out_size) {
    const float* x  = (const float*)d_in[0];
    const float* cs = (const float*)d_in[1];
    const float* W  = (const float*)d_in[2];
    float* out = (float*)d_out;
    (void)in_sizes; (void)n_in; (void)out_size;

    int nsm = 148;
    cudaDeviceGetAttribute(&nsm, cudaDevAttrMultiProcessorCount, 0);
    int chunk = (E_N + nsm - 1) / nsm;

    wsum_part_kernel<<<dim3(R_N, 4), O_N>>>(W);
    rgcn_main_kernel<<<nsm, 256>>>(x, cs, out, chunk);
}

// round 3
// speedup vs baseline: 1.5169x; 1.5169x over previous
#include <cuda_runtime.h>
#include <cuda_fp16.h>
#include <cstdint>

#define E_N 100000
#define R_N 64
#define I_N 256
#define O_N 256
#define TILE_M 128
#define N_TILES ((E_N + TILE_M - 1) / TILE_M)   // 782

// SMEM layout (dynamic):
//  s_w  : f32 Wsum [64][256]                     65536 B
//  s_ah : fp16 A-hi [128 rows][72 halfs(144B)]   18432 B
//  s_al : fp16 A-lo same                         18432 B
#define SM_W   0
#define SM_AH  65536
#define SM_AL  (SM_AH + 18432)
#define SM_TOT (SM_AL + 18432)   // 102400 B
#define A_STRIDE 144             // bytes per A row  (144 % 128 == 16 -> conflict-free LDS)

__device__ float g_wpart[4 * R_N * O_N];

// ---------------------------------------------------------------------------
// Kernel 1: partial reduction of W over i (r = blockIdx.x, i-quarter = blockIdx.y)
// ---------------------------------------------------------------------------
__global__ void wsum_part_kernel(const float* __restrict__ W) {
    const int r = blockIdx.x;
    const int part = blockIdx.y;
    const int o = threadIdx.x;
    const float* base = W + ((size_t)(r * I_N + part * 64)) * O_N + o;
    float s = 0.f;
#pragma unroll 16
    for (int i = 0; i < 64; ++i) s += base[(size_t)i * O_N];
    g_wpart[(part * R_N + r) * O_N + o] = s;
}

// ---------------------------------------------------------------------------
static __device__ __forceinline__ void mma16816(float* acc, const uint32_t* a,
                                                uint32_t b0, uint32_t b1) {
    asm volatile(
        "mma.sync.aligned.m16n8k16.row.col.f32.f16.f16.f32 "
        "{%0,%1,%2,%3}, {%4,%5,%6,%7}, {%8,%9}, {%0,%1,%2,%3};"
        : "+f"(acc[0]), "+f"(acc[1]), "+f"(acc[2]), "+f"(acc[3])
        : "r"(a[0]), "r"(a[1]), "r"(a[2]), "r"(a[3]), "r"(b0), "r"(b1));
}
static __device__ __forceinline__ uint32_t pack2(__half a, __half b) {
    __half2 h; h.x = a; h.y = b;
    return *(uint32_t*)&h;
}
static __device__ __forceinline__ void split16(float v, __half& hi, __half& lo) {
    hi = __float2half_rn(v);
    lo = __float2half_rn(v - __half2float(hi));
}

// ---------------------------------------------------------------------------
// Main persistent kernel: 256 threads, 8 warps; warp w owns output columns
// [32w, 32w+32).  Per tile: prep A (xsum/cs -> fp16 hi/lo) -> HMMA -> store.
// ---------------------------------------------------------------------------
__global__ __launch_bounds__(256, 1)
void rgcn_hmma_kernel(const float* __restrict__ x,
                      const float* __restrict__ cs,
                      float* __restrict__ out) {
    extern __shared__ __align__(16) char sm[];
    float* s_w = (float*)(sm + SM_W);
    char* s_ah = sm + SM_AH;
    char* s_al = sm + SM_AL;

    const int t = threadIdx.x;
    const int warp = t >> 5;
    const int lane = t & 31;

    // ---- build Wsum f32 in smem (coalesced, one pass) ----------------------
#pragma unroll 4
    for (int i = 0; i < 64; ++i) {
        int idx = i * 256 + t;             // = r*256 + o
        s_w[idx] = g_wpart[idx] + g_wpart[16384 + idx]
                 + g_wpart[32768 + idx] + g_wpart[49152 + idx];
    }
    __syncthreads();

    // ---- extract this thread's B fragments (held in registers forever) ----
    // B frag (col) for n-tile nt, k-step ks: rows kb,kb+1,kb+8,kb+9 at col n.
    uint32_t bh[4][4][2], bl[4][4][2];
    {
        const int n = warp * 32 + (lane >> 2);   // +8*nt added below
#pragma unroll
        for (int nt = 0; nt < 4; ++nt) {
#pragma unroll
            for (int ks = 0; ks < 4; ++ks) {
                int kb = ks * 16 + 2 * (lane & 3);
                int nn = n + nt * 8;
                float w00 = s_w[kb * 256 + nn];
                float w01 = s_w[(kb + 1) * 256 + nn];
                float w10 = s_w[(kb + 8) * 256 + nn];
                float w11 = s_w[(kb + 9) * 256 + nn];
                __half h00, l00, h01, l01, h10, l10, h11, l11;
                split16(w00, h00, l00); split16(w01, h01, l01);
                split16(w10, h10, l10); split16(w11, h11, l11);
                bh[nt][ks][0] = pack2(h00, h01); bh[nt][ks][1] = pack2(h10, h11);
                bl[nt][ks][0] = pack2(l00, l01); bl[nt][ks][1] = pack2(l10, l11);
            }
        }
    }
    __syncthreads();   // s_w dead; s_a region writable

    const int grid = gridDim.x;

    // prep mapping: entity row el = t>>1, k-half kh = t&1 (32 k each)
    const int el = t >> 1;
    const int kh = t & 1;

    for (int ti = blockIdx.x; ti < N_TILES; ti += grid) {
        const int ebase = ti * TILE_M;

        // ================= PREP: xsum + a-split ============================
        {
            int e = ebase + el;
            if (e > E_N - 1) e = E_N - 1;
            // xsum: this thread sums half the x row (128 floats)
            const float4* xp = (const float4*)x + (size_t)e * 64 + kh * 32;
            float a0 = 0.f, a1 = 0.f, a2 = 0.f, a3 = 0.f;
#pragma unroll
            for (int i = 0; i < 32; i += 4) {
                float4 v0 = xp[i], v1 = xp[i + 1], v2 = xp[i + 2], v3 = xp[i + 3];
                a0 += (v0.x + v0.y) + (v0.z + v0.w);
                a1 += (v1.x + v1.y) + (v1.z + v1.w);
                a2 += (v2.x + v2.y) + (v2.z + v2.w);
                a3 += (v3.x + v3.y) + (v3.z + v3.w);
            }
            float half_sum = (a0 + a1) + (a2 + a3);
            float xs = half_sum + __shfl_xor_sync(0xffffffffu, half_sum, 1);

            // a[e][k] = xs / cs[e][k] for k in [32*kh, 32*kh+32)
            const float4* cp = (const float4*)cs + (size_t)e * 16 + kh * 8;
            uint32_t hw[16], lw[16];   // 32 halfs hi, 32 halfs lo (packed)
#pragma unroll
            for (int q = 0; q < 8; ++q) {
                float4 c = cp[q];
                float v0 = __fdividef(xs, c.x);
                float v1 = __fdividef(xs, c.y);
                float v2 = __fdividef(xs, c.z);
                float v3 = __fdividef(xs, c.w);
                __half h0, l0, h1, l1, h2, l2, h3, l3;
                split16(v0, h0, l0); split16(v1, h1, l1);
                split16(v2, h2, l2); split16(v3, h3, l3);
                hw[2 * q] = pack2(h0, h1); hw[2 * q + 1] = pack2(h2, h3);
                lw[2 * q] = pack2(l0, l1); lw[2 * q + 1] = pack2(l2, l3);
            }
            uint32_t off = el * A_STRIDE + kh * 64;
            uint4* dh = (uint4*)(s_ah + off);
            uint4* dl = (uint4*)(s_al + off);
#pragma unroll
            for (int q = 0; q < 4; ++q) {
                dh[q] = make_uint4(hw[4 * q], hw[4 * q + 1], hw[4 * q + 2], hw[4 * q + 3]);
                dl[q] = make_uint4(lw[4 * q], lw[4 * q + 1], lw[4 * q + 2], lw[4 * q + 3]);
            }
        }
        __syncthreads();   // A tile ready

        // ================= MMA + STORE =====================================
        {
            const int gr = lane >> 2;            // 0..7
            const int cb = (lane & 3) * 4;       // byte offset of col pair
#pragma unroll 1
            for (int m0 = 0; m0 < TILE_M; m0 += 16) {
                // load A fragments for all 4 k-steps, hi and lo
                uint32_t ah[4][4], al[4][4];
                uint32_t base0 = (m0 + gr) * A_STRIDE + cb;
#pragma unroll
                for (int ks = 0; ks < 4; ++ks) {
                    uint32_t o0 = base0 + ks * 32;
                    ah[ks][0] = *(const uint32_t*)(s_ah + o0);
                    ah[ks][1] = *(const uint32_t*)(s_ah + o0 + 8 * A_STRIDE);
                    ah[ks][2] = *(const uint32_t*)(s_ah + o0 + 16);
                    ah[ks][3] = *(const uint32_t*)(s_ah + o0 + 8 * A_STRIDE + 16);
                    al[ks][0] = *(const uint32_t*)(s_al + o0);
                    al[ks][1] = *(const uint32_t*)(s_al + o0 + 8 * A_STRIDE);
                    al[ks][2] = *(const uint32_t*)(s_al + o0 + 16);
                    al[ks][3] = *(const uint32_t*)(s_al + o0 + 8 * A_STRIDE + 16);
                }

                float acc[4][4];
#pragma unroll
                for (int nt = 0; nt < 4; ++nt) {
                    acc[nt][0] = acc[nt][1] = acc[nt][2] = acc[nt][3] = 0.f;
#pragma unroll
                    for (int ks = 0; ks < 4; ++ks) {
                        mma16816(acc[nt], ah[ks], bh[nt][ks][0], bh[nt][ks][1]);
                        mma16816(acc[nt], ah[ks], bl[nt][ks][0], bl[nt][ks][1]);
                        mma16816(acc[nt], al[ks], bh[nt][ks][0], bh[nt][ks][1]);
                    }
                }

                // store D fragments
                int e0 = ebase + m0 + gr;
                int e1 = e0 + 8;
                int col = warp * 32 + (lane & 3) * 2;
                if (e0 < E_N) {
                    float* p = out + (size_t)e0 * O_N + col;
#pragma unroll
                    for (int nt = 0; nt < 4; ++nt)
                        *(float2*)(p + nt * 8) = make_float2(acc[nt][0], acc[nt][1]);
                }
                if (e1 < E_N) {
                    float* p = out + (size_t)e1 * O_N + col;
#pragma unroll
                    for (int nt = 0; nt < 4; ++nt)
                        *(float2*)(p + nt * 8) = make_float2(acc[nt][2], acc[nt][3]);
                }
            }
        }
        __syncthreads();   // protect s_a before next tile's prep
    }
}

// ---------------------------------------------------------------------------
// Inputs: x[E,256] f32, cs[E,64] f32, W[64,256,256] f32, edge_index (unused).
// Output: f32 [E,256].
// ---------------------------------------------------------------------------
extern "C" void kernel_launch(void* const* d_in, const int* in_sizes, int n_in,
                              void* d_out, int out_size) {
    const float* x  = (const float*)d_in[0];
    const float* cs = (const float*)d_in[1];
    const float* W  = (const float*)d_in[2];
    float* out = (float*)d_out;
    (void)in_sizes; (void)n_in; (void)out_size;

    int nsm = 148;
    cudaDeviceGetAttribute(&nsm, cudaDevAttrMultiProcessorCount, 0);

    cudaFuncSetAttribute(rgcn_hmma_kernel,
                         cudaFuncAttributeMaxDynamicSharedMemorySize, SM_TOT);

    wsum_part_kernel<<<dim3(R_N, 4), O_N>>>(W);
    rgcn_hmma_kernel<<<nsm, 256, SM_TOT>>>(x, cs, out);
}

// round 4
// speedup vs baseline: 1.7231x; 1.1359x over previous
#include <cuda_runtime.h>
#include <cuda_fp16.h>
#include <cstdint>

#define E_N 100000
#define R_N 64
#define I_N 256
#define O_N 256
#define TILE_M 128
#define N_TILES ((E_N + TILE_M - 1) / TILE_M)   // 782

// ---------------------------------------------------------------------------
// Dynamic smem layout (main kernel).  s_w (init-only) overlaps the cs buffers.
//   csbuf[2]  : 2 x 32768  @ 0
//   xsbuf[2]  : 2 x 512    @ 65536
//   A bufs    : ah0, al0, ah1, al1  (18432 each, stride-144 rows) @ 66560
#define SM_CS0   0
#define SM_CS1   32768
#define SM_XS0   65536
#define SM_XS1   66048
#define SM_A     66560
#define A_BUF    18432
#define SM_TOT   (SM_A + 4 * A_BUF)   // 140288 B
#define A_STRIDE 144                  // 144%128==16 -> conflict-free LDSM/LDS

__device__ float g_wpart[4 * R_N * O_N];
__device__ float g_xsum[E_N];

// ---------------------------------------------------------------------------
// Kernel 1: partial reduction of W over i
// ---------------------------------------------------------------------------
__global__ void wsum_part_kernel(const float* __restrict__ W) {
    const int r = blockIdx.x;
    const int part = blockIdx.y;
    const int o = threadIdx.x;
    const float* base = W + ((size_t)(r * I_N + part * 64)) * O_N + o;
    float s = 0.f;
#pragma unroll 16
    for (int i = 0; i < 64; ++i) s += base[(size_t)i * O_N];
    g_wpart[(part * R_N + r) * O_N + o] = s;
}

// ---------------------------------------------------------------------------
// Kernel 2: x row sums (pure streaming). One warp per entity row.
// ---------------------------------------------------------------------------
__global__ __launch_bounds__(256, 8)
void xsum_kernel(const float* __restrict__ x) {
    const int warp = threadIdx.x >> 5, lane = threadIdx.x & 31;
    const int row = blockIdx.x * 8 + warp;
    if (row >= E_N) return;
    const float4* xp = (const float4*)x + (size_t)row * 64;
    float4 v0 = xp[lane], v1 = xp[lane + 32];
    float s = (v0.x + v0.y) + (v0.z + v0.w) + (v1.x + v1.y) + (v1.z + v1.w);
#pragma unroll
    for (int d = 16; d; d >>= 1) s += __shfl_xor_sync(0xffffffffu, s, d);
    if (lane == 0) g_xsum[row] = s;
}

// ---------------------------------------------------------------------------
// helpers
// ---------------------------------------------------------------------------
static __device__ __forceinline__ void mma16816(float* acc, const uint32_t* a,
                                                uint32_t b0, uint32_t b1) {
    asm volatile(
        "mma.sync.aligned.m16n8k16.row.col.f32.f16.f16.f32 "
        "{%0,%1,%2,%3}, {%4,%5,%6,%7}, {%8,%9}, {%0,%1,%2,%3};"
        : "+f"(acc[0]), "+f"(acc[1]), "+f"(acc[2]), "+f"(acc[3])
        : "r"(a[0]), "r"(a[1]), "r"(a[2]), "r"(a[3]), "r"(b0), "r"(b1));
}
static __device__ __forceinline__ void ldsm4(uint32_t* r, uint32_t saddr) {
    asm volatile("ldmatrix.sync.aligned.m8n8.x4.shared.b16 {%0,%1,%2,%3}, [%4];"
                 : "=r"(r[0]), "=r"(r[1]), "=r"(r[2]), "=r"(r[3]) : "r"(saddr));
}
static __device__ __forceinline__ uint32_t pack2(__half a, __half b) {
    __half2 h; h.x = a; h.y = b;
    return *(uint32_t*)&h;
}
static __device__ __forceinline__ void split16(float v, __half& hi, __half& lo) {
    hi = __float2half_rn(v);
    lo = __float2half_rn(v - __half2float(hi));
}
// fast reciprocal: magic seed + 2 Newton iters, all on the FMA pipe (no MUFU)
static __device__ __forceinline__ float frcp(float y) {
    float r = __uint_as_float(0x7EF311C3u - __float_as_uint(y));
    r = r * __fmaf_rn(-y, r, 2.0f);
    r = r * __fmaf_rn(-y, r, 2.0f);
    return r;
}
static __device__ __forceinline__ void cp16(uint32_t dst, const void* src,
                                            uint32_t sz) {
    asm volatile("cp.async.cg.shared.global [%0], [%1], 16, %2;"
                 :: "r"(dst), "l"(src), "r"(sz) : "memory");
}
static __device__ __forceinline__ void cp4(uint32_t dst, const void* src,
                                           uint32_t sz) {
    asm volatile("cp.async.ca.shared.global [%0], [%1], 4, %2;"
                 :: "r"(dst), "l"(src), "r"(sz) : "memory");
}

// ---------------------------------------------------------------------------
// Kernel 3: persistent main kernel. 256 threads / 8 warps; warp w owns output
// columns [32w, 32w+32).  cs + xsum prefetched via double-buffered cp.async;
// A tiles double-buffered; A fragments via ldmatrix.
// ---------------------------------------------------------------------------
__global__ __launch_bounds__(256, 1)
void rgcn_hmma_kernel(const float* __restrict__ cs,
                      float* __restrict__ out) {
    extern __shared__ __align__(16) char sm[];
    const uint32_t sbase = (uint32_t)__cvta_generic_to_shared(sm);
    const int t = threadIdx.x;
    const int warp = t >> 5, lane = t & 31;

    // ---- init: Wsum in smem (offset 0, init-only), extract B fragments ----
    float* s_w = (float*)sm;
#pragma unroll 4
    for (int i = 0; i < 64; ++i) {
        int idx = i * 256 + t;
        s_w[idx] = g_wpart[idx] + g_wpart[16384 + idx]
                 + g_wpart[32768 + idx] + g_wpart[49152 + idx];
    }
    __syncthreads();

    uint32_t bh[4][4][2], bl[4][4][2];
    {
        const int n = warp * 32 + (lane >> 2);
#pragma unroll
        for (int nt = 0; nt < 4; ++nt)
#pragma unroll
            for (int ks = 0; ks < 4; ++ks) {
                int kb = ks * 16 + 2 * (lane & 3);
                int nn = n + nt * 8;
                float w00 = s_w[kb * 256 + nn];
                float w01 = s_w[(kb + 1) * 256 + nn];
                float w10 = s_w[(kb + 8) * 256 + nn];
                float w11 = s_w[(kb + 9) * 256 + nn];
                __half h00, l00, h01, l01, h10, l10, h11, l11;
                split16(w00, h00, l00); split16(w01, h01, l01);
                split16(w10, h10, l10); split16(w11, h11, l11);
                bh[nt][ks][0] = pack2(h00, h01); bh[nt][ks][1] = pack2(h10, h11);
                bl[nt][ks][0] = pack2(l00, l01); bl[nt][ks][1] = pack2(l10, l11);
            }
    }
    __syncthreads();   // s_w dead; csbuf region reusable

    const int grid = gridDim.x;
    const size_t cs_bytes = (size_t)E_N * 64 * 4;

    // cs/xs prefetch issue helper (inlined twice below)
#define ISSUE_TILE(TI, BUF)                                                   \
    {                                                                         \
        size_t gb = (size_t)(TI) * TILE_M * 256;                              \
        uint32_t cdst = sbase + ((BUF) ? SM_CS1 : SM_CS0);                    \
        const char* csrc = (const char*)cs + gb;                              \
        _Pragma("unroll")                                                     \
        for (int i = 0; i < 8; ++i) {                                         \
            uint32_t co = (uint32_t)(i * 256 + t) * 16;                       \
            uint32_t ok = (gb + co + 16 <= cs_bytes) ? 16u : 0u;              \
            cp16(cdst + co, csrc + co, ok);                                   \
        }                                                                     \
        if (t < 128) {                                                        \
            int e = (TI) * TILE_M + t;                                        \
            cp4(sbase + ((BUF) ? SM_XS1 : SM_XS0) + t * 4, &g_xsum[e],        \
                e < E_N ? 4u : 0u);                                           \
        }                                                                     \
    }

    // prologue: first tile's cs/xs into buffer 0
    if (blockIdx.x < N_TILES) ISSUE_TILE(blockIdx.x, 0);
    asm volatile("cp.async.commit_group;" ::: "memory");

    const int el = t >> 1, kh = t & 1;   // prep mapping
    int cur = 0;

    for (int ti = blockIdx.x; ti < N_TILES; ti += grid) {
        // issue next tile's prefetch, then wait for current buffer
        int nxt = ti + grid;
        if (nxt < N_TILES) ISSUE_TILE(nxt, cur ^ 1);
        asm volatile("cp.async.commit_group;" ::: "memory");
        asm volatile("cp.async.wait_group 1;" ::: "memory");
        __syncthreads();

        // ================= PREP: a = xs * (1/cs), fp16 hi/lo split ==========
        {
            const float* xsb = (const float*)(sm + (cur ? SM_XS1 : SM_XS0));
            const float4* cb = (const float4*)(sm + (cur ? SM_CS1 : SM_CS0));
            float xs = xsb[el];
            const float4* cp = cb + el * 16 + kh * 8;
            uint32_t hw[16], lw[16];
#pragma unroll
            for (int q = 0; q < 8; ++q) {
                float4 c = cp[q];
                float v0 = xs * frcp(c.x);
                float v1 = xs * frcp(c.y);
                float v2 = xs * frcp(c.z);
                float v3 = xs * frcp(c.w);
                __half h0, l0, h1, l1, h2, l2, h3, l3;
                split16(v0, h0, l0); split16(v1, h1, l1);
                split16(v2, h2, l2); split16(v3, h3, l3);
                hw[2 * q] = pack2(h0, h1); hw[2 * q + 1] = pack2(h2, h3);
                lw[2 * q] = pack2(l0, l1); lw[2 * q + 1] = pack2(l2, l3);
            }
            char* ah = sm + SM_A + (cur ? 2 * A_BUF : 0);
            char* al = ah + A_BUF;
            uint32_t off = el * A_STRIDE + kh * 64;
            uint4* dh = (uint4*)(ah + off);
            uint4* dl = (uint4*)(al + off);
#pragma unroll
            for (int q = 0; q < 4; ++q) {
                dh[q] = make_uint4(hw[4 * q], hw[4 * q + 1], hw[4 * q + 2], hw[4 * q + 3]);
                dl[q] = make_uint4(lw[4 * q], lw[4 * q + 1], lw[4 * q + 2], lw[4 * q + 3]);
            }
        }
        __syncthreads();   // A[cur] ready

        // ================= MMA + STORE =====================================
        {
            const uint32_t ah_base = sbase + SM_A + (cur ? 2 * A_BUF : 0);
            const uint32_t al_base = ah_base + A_BUF;
            const int ebase = ti * TILE_M;
            // ldmatrix lane address components
            const uint32_t lrow = (lane & 7) + ((lane >> 3) & 1) * 8;
            const uint32_t lcol = (lane >> 4) * 16;
            const int gr = lane >> 2;
            const int col = warp * 32 + (lane & 3) * 2;

#pragma unroll 1
            for (int m0 = 0; m0 < TILE_M; m0 += 16) {
                uint32_t fo = (m0 + lrow) * A_STRIDE + lcol;
                uint32_t ah[4][4], al[4][4];
#pragma unroll
                for (int ks = 0; ks < 4; ++ks) {
                    ldsm4(ah[ks], ah_base + fo + ks * 32);
                    ldsm4(al[ks], al_base + fo + ks * 32);
                }
                float acc[4][4];
#pragma unroll
                for (int nt = 0; nt < 4; ++nt) {
                    acc[nt][0] = acc[nt][1] = acc[nt][2] = acc[nt][3] = 0.f;
#pragma unroll
                    for (int ks = 0; ks < 4; ++ks) {
                        mma16816(acc[nt], ah[ks], bh[nt][ks][0], bh[nt][ks][1]);
                        mma16816(acc[nt], ah[ks], bl[nt][ks][0], bl[nt][ks][1]);
                        mma16816(acc[nt], al[ks], bh[nt][ks][0], bh[nt][ks][1]);
                    }
                }
                int e0 = ebase + m0 + gr, e1 = e0 + 8;
                if (e0 < E_N) {
                    float* p = out + (size_t)e0 * O_N + col;
#pragma unroll
                    for (int nt = 0; nt < 4; ++nt)
                        *(float2*)(p + nt * 8) = make_float2(acc[nt][0], acc[nt][1]);
                }
                if (e1 < E_N) {
                    float* p = out + (size_t)e1 * O_N + col;
#pragma unroll
                    for (int nt = 0; nt < 4; ++nt)
                        *(float2*)(p + nt * 8) = make_float2(acc[nt][2], acc[nt][3]);
                }
            }
        }
        cur ^= 1;
        __syncthreads();   // A[cur^1] fully consumed before next prep writes
    }
#undef ISSUE_TILE
}

// ---------------------------------------------------------------------------
// Inputs: x[E,256] f32, cs[E,64] f32, W[64,256,256] f32, edge_index (unused).
// Output: f32 [E,256].
// ---------------------------------------------------------------------------
extern "C" void kernel_launch(void* const* d_in, const int* in_sizes, int n_in,
                              void* d_out, int out_size) {
    const float* x  = (const float*)d_in[0];
    const float* cs = (const float*)d_in[1];
    const float* W  = (const float*)d_in[2];
    float* out = (float*)d_out;
    (void)in_sizes; (void)n_in; (void)out_size;

    int nsm = 148;
    cudaDeviceGetAttribute(&nsm, cudaDevAttrMultiProcessorCount, 0);

    cudaFuncSetAttribute(rgcn_hmma_kernel,
                         cudaFuncAttributeMaxDynamicSharedMemorySize, SM_TOT);

    wsum_part_kernel<<<dim3(R_N, 4), O_N>>>(W);
    xsum_kernel<<<(E_N + 7) / 8, 256>>>(x);
    rgcn_hmma_kernel<<<nsm, 256, SM_TOT>>>(cs, out);
}

// round 5
// speedup vs baseline: 1.9101x; 1.1085x over previous
#include <cuda_runtime.h>
#include <cuda_fp16.h>
#include <cstdint>

#define E_N 100000
#define R_N 64
#define I_N 256
#define O_N 256
#define TILE_M 128
#define N_TILES ((E_N + TILE_M - 1) / TILE_M)   // 782

// fused kernel 1 block split
#define WSUM_BLOCKS 1024                         // (r, i-16th) pairs
#define XSUM_BLOCKS ((E_N + 7) / 8)              // 12500
#define FUSE_BLOCKS (WSUM_BLOCKS + XSUM_BLOCKS)

// ---------------------------------------------------------------------------
// Main-kernel dynamic smem (103424 B -> 2 CTAs/SM):
//   cs double buffer 2x32768 @0, xs double buffer 2x512 @65536,
//   A hi/lo single buffer @66560 (stride-144 rows).
//   init-only s_w (64KB) overlaps the cs buffers.
#define SM_CS0   0
#define SM_CS1   32768
#define SM_XS0   65536
#define SM_XS1   66048
#define SM_A     66560
#define A_BUF    18432
#define SM_TOT   (SM_A + 2 * A_BUF)   // 103424
#define A_STRIDE 144                  // %128==16 -> conflict-free LDSM

__device__ float g_wpart[16 * R_N * O_N];   // 1 MB partials
__device__ float g_wsum[R_N * O_N];
__device__ float g_xsum[E_N];

// ---------------------------------------------------------------------------
// Kernel 1 (fused): blocks [0,1024) -> W partial sums; rest -> x row sums.
// ---------------------------------------------------------------------------
__global__ __launch_bounds__(256, 8)
void fused_stream_kernel(const float* __restrict__ W,
                         const float* __restrict__ x) {
    const int bid = blockIdx.x;
    if (bid < WSUM_BLOCKS) {
        const int r = bid & 63;
        const int part = bid >> 6;           // 0..15, 16 i-rows each
        const int o = threadIdx.x;
        const float* base = W + ((size_t)(r * I_N + part * 16)) * O_N + o;
        float s = 0.f;
#pragma unroll
        for (int i = 0; i < 16; ++i) s += base[(size_t)i * O_N];
        g_wpart[(part * R_N + r) * O_N + o] = s;
    } else {
        const int warp = threadIdx.x >> 5, lane = threadIdx.x & 31;
        const int row = (bid - WSUM_BLOCKS) * 8 + warp;
        if (row >= E_N) return;
        const float4* xp = (const float4*)x + (size_t)row * 64;
        float4 v0 = xp[lane], v1 = xp[lane + 32];
        float s = (v0.x + v0.y) + (v0.z + v0.w) + (v1.x + v1.y) + (v1.z + v1.w);
#pragma unroll
        for (int d = 16; d; d >>= 1) s += __shfl_xor_sync(0xffffffffu, s, d);
        if (lane == 0) g_xsum[row] = s;
    }
}

// ---------------------------------------------------------------------------
// Kernel 2: collapse 16 W partials -> g_wsum (1 MB, L2-resident).
// ---------------------------------------------------------------------------
__global__ void wsum_final_kernel() {
    const int r = blockIdx.x, o = threadIdx.x;
    float s = 0.f;
#pragma unroll
    for (int p = 0; p < 16; ++p) s += g_wpart[(p * R_N + r) * O_N + o];
    g_wsum[r * O_N + o] = s;
}

// ---------------------------------------------------------------------------
// helpers
// ---------------------------------------------------------------------------
static __device__ __forceinline__ void mma16816(float* acc, const uint32_t* a,
                                                uint32_t b0, uint32_t b1) {
    asm volatile(
        "mma.sync.aligned.m16n8k16.row.col.f32.f16.f16.f32 "
        "{%0,%1,%2,%3}, {%4,%5,%6,%7}, {%8,%9}, {%0,%1,%2,%3};"
        : "+f"(acc[0]), "+f"(acc[1]), "+f"(acc[2]), "+f"(acc[3])
        : "r"(a[0]), "r"(a[1]), "r"(a[2]), "r"(a[3]), "r"(b0), "r"(b1));
}
static __device__ __forceinline__ void ldsm4(uint32_t* r, uint32_t saddr) {
    asm volatile("ldmatrix.sync.aligned.m8n8.x4.shared.b16 {%0,%1,%2,%3}, [%4];"
                 : "=r"(r[0]), "=r"(r[1]), "=r"(r[2]), "=r"(r[3]) : "r"(saddr));
}
static __device__ __forceinline__ uint32_t pack2(__half a, __half b) {
    __half2 h; h.x = a; h.y = b;
    return *(uint32_t*)&h;
}
static __device__ __forceinline__ void split16(float v, __half& hi, __half& lo) {
    hi = __float2half_rn(v);
    lo = __float2half_rn(v - __half2float(hi));
}
// FMA-pipe reciprocal (no MUFU): magic seed + 2 Newton iterations
static __device__ __forceinline__ float frcp(float y) {
    float r = __uint_as_float(0x7EF311C3u - __float_as_uint(y));
    r = r * __fmaf_rn(-y, r, 2.0f);
    r = r * __fmaf_rn(-y, r, 2.0f);
    return r;
}
static __device__ __forceinline__ void cp16(uint32_t dst, const void* src,
                                            uint32_t sz) {
    asm volatile("cp.async.cg.shared.global [%0], [%1], 16, %2;"
                 :: "r"(dst), "l"(src), "r"(sz) : "memory");
}
static __device__ __forceinline__ void cp4(uint32_t dst, const void* src,
                                           uint32_t sz) {
    asm volatile("cp.async.ca.shared.global [%0], [%1], 4, %2;"
                 :: "r"(dst), "l"(src), "r"(sz) : "memory");
}

// ---------------------------------------------------------------------------
// Kernel 3: persistent main kernel, 2 CTAs/SM. 8 warps; warp w owns output
// columns [32w,32w+32). Single A buffer; cs/xs double-buffered via cp.async.
// ---------------------------------------------------------------------------
__global__ __launch_bounds__(256, 2)
void rgcn_hmma_kernel(const float* __restrict__ cs,
                      float* __restrict__ out) {
    extern __shared__ __align__(16) char sm[];
    const uint32_t sbase = (uint32_t)__cvta_generic_to_shared(sm);
    const int t = threadIdx.x;
    const int warp = t >> 5, lane = t & 31;

    // ---- init: stage Wsum in smem (overlaps cs bufs), extract B frags -----
    float* s_w = (float*)sm;
#pragma unroll 4
    for (int i = 0; i < 64; ++i) {
        int idx = i * 256 + t;
        s_w[idx] = g_wsum[idx];
    }
    __syncthreads();

    uint32_t bh[4][4][2], bl[4][4][2];
    {
        const int n = warp * 32 + (lane >> 2);
#pragma unroll
        for (int nt = 0; nt < 4; ++nt)
#pragma unroll
            for (int ks = 0; ks < 4; ++ks) {
                int kb = ks * 16 + 2 * (lane & 3);
                int nn = n + nt * 8;
                float w00 = s_w[kb * 256 + nn];
                float w01 = s_w[(kb + 1) * 256 + nn];
                float w10 = s_w[(kb + 8) * 256 + nn];
                float w11 = s_w[(kb + 9) * 256 + nn];
                __half h00, l00, h01, l01, h10, l10, h11, l11;
                split16(w00, h00, l00); split16(w01, h01, l01);
                split16(w10, h10, l10); split16(w11, h11, l11);
                bh[nt][ks][0] = pack2(h00, h01); bh[nt][ks][1] = pack2(h10, h11);
                bl[nt][ks][0] = pack2(l00, l01); bl[nt][ks][1] = pack2(l10, l11);
            }
    }
    __syncthreads();   // s_w dead; cs buffers reusable

    const int grid = gridDim.x;
    const size_t cs_bytes = (size_t)E_N * 64 * 4;

#define ISSUE_TILE(TI, BUF)                                                   \
    {                                                                         \
        size_t gb = (size_t)(TI) * TILE_M * 256;                              \
        uint32_t cdst = sbase + ((BUF) ? SM_CS1 : SM_CS0);                    \
        const char* csrc = (const char*)cs + gb;                              \
        _Pragma("unroll")                                                     \
        for (int i = 0; i < 8; ++i) {                                         \
            uint32_t co = (uint32_t)(i * 256 + t) * 16;                       \
            uint32_t ok = (gb + co + 16 <= cs_bytes) ? 16u : 0u;              \
            cp16(cdst + co, csrc + co, ok);                                   \
        }                                                                     \
        if (t < 128) {                                                        \
            int e = (TI) * TILE_M + t;                                        \
            cp4(sbase + ((BUF) ? SM_XS1 : SM_XS0) + t * 4, &g_xsum[e],        \
                e < E_N ? 4u : 0u);                                           \
        }                                                                     \
    }

    if (blockIdx.x < N_TILES) ISSUE_TILE(blockIdx.x, 0);
    asm volatile("cp.async.commit_group;" ::: "memory");

    const int el = t >> 1, kh = t & 1;
    int cur = 0;

    for (int ti = blockIdx.x; ti < N_TILES; ti += grid) {
        int nxt = ti + grid;
        if (nxt < N_TILES) ISSUE_TILE(nxt, cur ^ 1);
        asm volatile("cp.async.commit_group;" ::: "memory");
        asm volatile("cp.async.wait_group 1;" ::: "memory");
        __syncthreads();   // cs[cur] ready; prev MMA done reading A

        // ================= PREP: a = xs * (1/cs), fp16 hi/lo ================
        {
            const float* xsb = (const float*)(sm + (cur ? SM_XS1 : SM_XS0));
            const float4* cb = (const float4*)(sm + (cur ? SM_CS1 : SM_CS0));
            float xs = xsb[el];
            const float4* cp = cb + el * 16 + kh * 8;
            uint32_t hw[16], lw[16];
#pragma unroll
            for (int q = 0; q < 8; ++q) {
                float4 c = cp[q];
                float v0 = xs * frcp(c.x);
                float v1 = xs * frcp(c.y);
                float v2 = xs * frcp(c.z);
                float v3 = xs * frcp(c.w);
                __half h0, l0, h1, l1, h2, l2, h3, l3;
                split16(v0, h0, l0); split16(v1, h1, l1);
                split16(v2, h2, l2); split16(v3, h3, l3);
                hw[2 * q] = pack2(h0, h1); hw[2 * q + 1] = pack2(h2, h3);
                lw[2 * q] = pack2(l0, l1); lw[2 * q + 1] = pack2(l2, l3);
            }
            uint32_t off = el * A_STRIDE + kh * 64;
            uint4* dh = (uint4*)(sm + SM_A + off);
            uint4* dl = (uint4*)(sm + SM_A + A_BUF + off);
#pragma unroll
            for (int q = 0; q < 4; ++q) {
                dh[q] = make_uint4(hw[4 * q], hw[4 * q + 1], hw[4 * q + 2], hw[4 * q + 3]);
                dl[q] = make_uint4(lw[4 * q], lw[4 * q + 1], lw[4 * q + 2], lw[4 * q + 3]);
            }
        }
        __syncthreads();   // A ready

        // ================= MMA + STORE =====================================
        {
            const uint32_t ah_base = sbase + SM_A;
            const uint32_t al_base = ah_base + A_BUF;
            const int ebase = ti * TILE_M;
            const uint32_t lrow = (lane & 7) + ((lane >> 3) & 1) * 8;
            const uint32_t lcol = (lane >> 4) * 16;
            const int gr = lane >> 2;
            const int col = warp * 32 + (lane & 3) * 2;

#pragma unroll 1
            for (int m0 = 0; m0 < TILE_M; m0 += 16) {
                uint32_t fo = (m0 + lrow) * A_STRIDE + lcol;
                float acc[4][4];
#pragma unroll
                for (int nt = 0; nt < 4; ++nt)
                    acc[nt][0] = acc[nt][1] = acc[nt][2] = acc[nt][3] = 0.f;
#pragma unroll
                for (int ks = 0; ks < 4; ++ks) {
                    uint32_t ah[4], al[4];
                    ldsm4(ah, ah_base + fo + ks * 32);
                    ldsm4(al, al_base + fo + ks * 32);
#pragma unroll
                    for (int nt = 0; nt < 4; ++nt) {
                        mma16816(acc[nt], ah, bh[nt][ks][0], bh[nt][ks][1]);
                        mma16816(acc[nt], ah, bl[nt][ks][0], bl[nt][ks][1]);
                        mma16816(acc[nt], al, bh[nt][ks][0], bh[nt][ks][1]);
                    }
                }
                int e0 = ebase + m0 + gr, e1 = e0 + 8;
                if (e0 < E_N) {
                    float* p = out + (size_t)e0 * O_N + col;
#pragma unroll
                    for (int nt = 0; nt < 4; ++nt)
                        *(float2*)(p + nt * 8) = make_float2(acc[nt][0], acc[nt][1]);
                }
                if (e1 < E_N) {
                    float* p = out + (size_t)e1 * O_N + col;
#pragma unroll
                    for (int nt = 0; nt < 4; ++nt)
                        *(float2*)(p + nt * 8) = make_float2(acc[nt][2], acc[nt][3]);
                }
            }
        }
        cur ^= 1;
        __syncthreads();   // A consumed before next prep overwrites
    }
#undef ISSUE_TILE
}

// ---------------------------------------------------------------------------
// Inputs: x[E,256] f32, cs[E,64] f32, W[64,256,256] f32, edge_index (unused).
// Output: f32 [E,256].
// ---------------------------------------------------------------------------
extern "C" void kernel_launch(void* const* d_in, const int* in_sizes, int n_in,
                              void* d_out, int out_size) {
    const float* x  = (const float*)d_in[0];
    const float* cs = (const float*)d_in[1];
    const float* W  = (const float*)d_in[2];
    float* out = (float*)d_out;
    (void)in_sizes; (void)n_in; (void)out_size;

    int nsm = 148;
    cudaDeviceGetAttribute(&nsm, cudaDevAttrMultiProcessorCount, 0);

    cudaFuncSetAttribute(rgcn_hmma_kernel,
                         cudaFuncAttributeMaxDynamicSharedMemorySize, SM_TOT);

    fused_stream_kernel<<<FUSE_BLOCKS, 256>>>(W, x);
    wsum_final_kernel<<<R_N, O_N>>>();
    rgcn_hmma_kernel<<<2 * nsm, 256, SM_TOT>>>(cs, out);
}